// round 17
// baseline (speedup 1.0000x reference)
#include <cuda_runtime.h>
#include <cuda_bf16.h>
#include <cstdint>

// Problem constants
constexpr int NB   = 128;   // batch
constexpr int NT   = 128;   // encoder time steps
constexpr int NIN  = 3;     // input features
constexpr int NH   = 512;   // hidden
constexpr int NTGT = 32;    // decoder steps

constexpr int ENC_CTAS = 256;   // 2 dirs x 8 bt x 16 jt, 2 CTAs/SM
constexpr int DEC_CTAS = 128;

// ---------------- encoder smem layout (R11/R12) ----------------
constexpr int EHS      = 520;                   // bf16 row stride (elements)
constexpr int E_UNION  = 32 * EHS * 2;          // W staging (32 rows) / h tile (16 rows)
constexpr int OFF_ESTG = 2 * E_UNION;           // [16][36] f32 stage
constexpr int OFF_EPRT = OFF_ESTG + 16 * 36 * 4;   // [4][16][36] f32 partials
constexpr int ENC_SMEM = OFF_EPRT + 4 * 16 * 36 * 4;   // 78080 B

// ---------------- decoder smem layout (R14: split W regions + sRec) --------
constexpr int DEHS     = 1032;                  // W row stride (1024 cols + pad)
constexpr int DHS      = 520;                   // h row stride (512 cols + pad)
constexpr int DW_TILE  = 32 * DEHS * 2;         // 66048 B per precision
constexpr int DH_TILE  = 16 * DHS * 2;          // 16640 B per precision
constexpr int OFF_DWHI = 0;
constexpr int OFF_DWLO = OFF_DWHI + DW_TILE;    // 66048
constexpr int OFF_DHHI = OFF_DWLO + DW_TILE;    // 132096
constexpr int OFF_DHLO = OFF_DHHI + DH_TILE;    // 148736
constexpr int OFF_DSTG = OFF_DHLO + DH_TILE;    // 165376  [16][36] f32
constexpr int OFF_DPRT = OFF_DSTG + 16 * 36 * 4;   // 167680 [2][16][36] f32 (B partials)
constexpr int OFF_DREC = OFF_DPRT + 2 * 16 * 36 * 4; // 172288 [4][2][16][36] f32
constexpr int DEC_SMEM = OFF_DREC + 4 * 2 * 16 * 36 * 4;  // 190720 B

constexpr int WMAT     = NH * NH;
constexpr int WIHR_OFF = 4 * WMAT;

// ---------------- xs1 mma smem layout (R12: double-buffered) ----------------
constexpr int XAS     = 72;
constexpr int X_SA    = 128 * XAS * 2;
constexpr int X_SB    = 64 * XAS * 2;
constexpr int X_STAGE = 2 * X_SA + 2 * X_SB;
constexpr int XS1_SMEM = 2 * X_STAGE;

// ---------------------------------------------------------------------------
// Static device scratch
// ---------------------------------------------------------------------------
__device__ __nv_bfloat16 g_l0hi[NT * NB * (2 * NH)];
__device__ __nv_bfloat16 g_l0lo[NT * NB * (2 * NH)];
__device__ __nv_bfloat16 g_xWhi[2 * NH * (2 * NH)];
__device__ __nv_bfloat16 g_xWlo[2 * NH * (2 * NH)];
__device__ float g_xs1[2 * NT * NB * NH];
__device__ __nv_bfloat16 g_hhi[2][2 * NB * NH];
__device__ __nv_bfloat16 g_hlo[2][2 * NB * NH];
__device__ __nv_bfloat16 g_dWhi[7 * WMAT];
__device__ __nv_bfloat16 g_dWlo[7 * WMAT];
__device__ __nv_bfloat16 g_dhhi[2][4 * NB * NH];
__device__ __nv_bfloat16 g_dhlo[2][4 * NB * NH];
__device__ float g_o0p[2][16 * NB];          // per-jt partial output dots
__device__ unsigned g_cnt;
__device__ unsigned g_gen;
__device__ unsigned g_gcnt[16 * 32];
__device__ unsigned g_ggen[16 * 32];

// ---------------------------------------------------------------------------
// Barriers (generation-based, self-resetting, replay-safe, leader fence)
// ---------------------------------------------------------------------------
__device__ __forceinline__ void grid_barrier(unsigned nctas)
{
    __syncthreads();
    if (threadIdx.x == 0) {
        __threadfence();
        volatile unsigned* genp = &g_gen;
        unsigned gen = *genp;
        if (atomicAdd(&g_cnt, 1u) == nctas - 1) {
            g_cnt = 0;
            __threadfence();
            *genp = gen + 1;
        } else {
            while (*genp == gen) { }
            __threadfence();
        }
    }
    __syncthreads();
}

__device__ __forceinline__ void group_barrier(int g, unsigned n)
{
    __syncthreads();
    if (threadIdx.x == 0) {
        __threadfence();
        volatile unsigned* genp = &g_ggen[g * 32];
        unsigned gen = *genp;
        if (atomicAdd(&g_gcnt[g * 32], 1u) == n - 1) {
            g_gcnt[g * 32] = 0;
            __threadfence();
            *genp = gen + 1;
        } else {
            while (*genp == gen) { }
            __threadfence();
        }
    }
    __syncthreads();
}

// ---------------------------------------------------------------------------
// mma.sync + cp.async helpers
// ---------------------------------------------------------------------------
__device__ __forceinline__ uint32_t s2u(const void* p)
{
    return (uint32_t)__cvta_generic_to_shared(p);
}

#define LDSM_X4(r0, r1, r2, r3, addr)                                          \
    asm volatile("ldmatrix.sync.aligned.m8n8.x4.shared.b16 {%0,%1,%2,%3}, [%4];" \
                 : "=r"(r0), "=r"(r1), "=r"(r2), "=r"(r3) : "r"(addr))

#define MMA_BF16(c0, c1, c2, c3, a0, a1, a2, a3, b0, b1)                       \
    asm volatile("mma.sync.aligned.m16n8k16.row.col.f32.bf16.bf16.f32 "        \
                 "{%0,%1,%2,%3}, {%4,%5,%6,%7}, {%8,%9}, {%0,%1,%2,%3};"       \
                 : "+f"(c0), "+f"(c1), "+f"(c2), "+f"(c3)                      \
                 : "r"(a0), "r"(a1), "r"(a2), "r"(a3), "r"(b0), "r"(b1))

#define CP_ASYNC16(saddr, gptr)                                                \
    asm volatile("cp.async.cg.shared.global [%0], [%1], 16;"                   \
                 :: "r"(saddr), "l"(gptr))
#define CP_COMMIT()  asm volatile("cp.async.commit_group;")
#define CP_WAIT0()   asm volatile("cp.async.wait_group 0;" ::: "memory")
#define CP_WAIT1()   asm volatile("cp.async.wait_group 1;" ::: "memory")

__device__ __forceinline__ void split_bf16(float v, __nv_bfloat16& hi, __nv_bfloat16& lo)
{
    hi = __float2bfloat16(v);
    lo = __float2bfloat16(v - __bfloat162float(hi));
}

// ---------------------------------------------------------------------------
// Pre-split Wih1 into bf16 hi/lo
// ---------------------------------------------------------------------------
__global__ void __launch_bounds__(256) split_wih1(const float* __restrict__ W)
{
    const int i = (blockIdx.x * 256 + threadIdx.x) * 4;
    if (i < 2 * NH * 2 * NH) {
        float4 w = *(const float4*)&W[i];
        split_bf16(w.x, g_xWhi[i + 0], g_xWlo[i + 0]);
        split_bf16(w.y, g_xWhi[i + 1], g_xWlo[i + 1]);
        split_bf16(w.z, g_xWhi[i + 2], g_xWlo[i + 2]);
        split_bf16(w.w, g_xWhi[i + 3], g_xWlo[i + 3]);
    }
}

// ---------------------------------------------------------------------------
// Persistent encoder layer (R14 = R12 h-staging + light barrier + init hoist)
// ---------------------------------------------------------------------------
__global__ void __launch_bounds__(256, 2) enc_mma(
    const float* __restrict__ x, const float* __restrict__ Wih0,
    const float* __restrict__ Whh_all, const float* __restrict__ bih,
    const float* __restrict__ bhh, int layer)
{
    extern __shared__ char sm[];
    __nv_bfloat16* sHhi = (__nv_bfloat16*)(sm);
    __nv_bfloat16* sHlo = (__nv_bfloat16*)(sm + E_UNION);
    float*         sStg = (float*)(sm + OFF_ESTG);
    float*         sPrt = (float*)(sm + OFF_EPRT);

    const int blk = blockIdx.x;
    const int d   = blk >> 7;
    const int rem = blk & 127;
    const int bt  = rem >> 4;
    const int jt  = rem & 15;
    const int grp = blk >> 4;
    const int b0  = bt * 16;
    const int j0  = jt * 32;
    const int tid = threadIdx.x;
    const int lane = tid & 31;
    const int warp = tid >> 5;
    const int kw   = warp & 3;
    const int mj   = warp >> 2;

    const float* Whh = Whh_all + d * NH * NH;

    // ---- one-time: stage W tile (bf16 hi/lo) into smem ----
    {
        const int r  = tid >> 3;
        const int c0 = (tid & 7) * 4;
        for (int k0 = 0; k0 < NH; k0 += 32) {
            float4 w = __ldg((const float4*)&Whh[(j0 + r) * NH + k0 + c0]);
            const int o = r * EHS + k0 + c0;
            split_bf16(w.x, sHhi[o + 0], sHlo[o + 0]);
            split_bf16(w.y, sHhi[o + 1], sHlo[o + 1]);
            split_bf16(w.z, sHhi[o + 2], sHlo[o + 2]);
            split_bf16(w.w, sHhi[o + 3], sHlo[o + 3]);
        }
    }
    __syncthreads();

    // ---- preload A fragments into registers ----
    uint32_t aHi[8][4], aLo[8][4];
    {
        const int ag = lane >> 3, ar = lane & 7;
        const uint32_t rowOff = (uint32_t)((mj * 16 + (ag & 1) * 8 + ar) * EHS) * 2;
        const uint32_t colSel = (uint32_t)(kw * 128 + (ag >> 1) * 8) * 2;
#pragma unroll
        for (int q = 0; q < 8; q++) {
            const uint32_t off = rowOff + colSel + q * 32;
            LDSM_X4(aHi[q][0], aHi[q][1], aHi[q][2], aHi[q][3], s2u(sHhi) + off);
            LDSM_X4(aLo[q][0], aLo[q][1], aLo[q][2], aLo[q][3], s2u(sHlo) + off);
        }
    }

    // ---- B (h) ldmatrix bases ----
    const uint32_t bOff = (uint32_t)(((lane >> 4) * 8 + (lane & 7)) * EHS
                                     + ((lane >> 3) & 1) * 8 + kw * 128) * 2;
    const uint32_t bHiBase = s2u(sHhi) + bOff;
    const uint32_t bLoBase = s2u(sHlo) + bOff;

    // ---- owner slots + layer-0 constants ----
    const int sr = tid >> 4;
    const int sj = (tid & 15) * 2;
    float bias0 = 0.f, bias1 = 0.f, wi[6];
    if (layer == 0) {
        bias0 = bih[d * NH + j0 + sj + 0] + bhh[d * NH + j0 + sj + 0];
        bias1 = bih[d * NH + j0 + sj + 1] + bhh[d * NH + j0 + sj + 1];
        const float* wp = Wih0 + (d * NH + j0 + sj) * NIN;
#pragma unroll
        for (int i = 0; i < 6; i++) wi[i] = wp[i];
    }

    // ---- stage init for t = 0 ----
    {
        const int td0 = d ? (NT - 1) : 0;
        float v0, v1;
        if (layer == 0) {
            const float* xr = x + ((b0 + sr) * NT + td0) * NIN;
            const float x0 = xr[0], x1 = xr[1], x2 = xr[2];
            v0 = bias0 + x0 * wi[0] + x1 * wi[1] + x2 * wi[2];
            v1 = bias1 + x0 * wi[3] + x1 * wi[4] + x2 * wi[5];
        } else {
            float2 v = __ldg((const float2*)&g_xs1[((d * NT + td0) * NB + b0 + sr) * NH + j0 + sj]);
            v0 = v.x; v1 = v.y;
        }
        sStg[sr * 36 + sj + 0] = v0;
        sStg[sr * 36 + sj + 1] = v1;
    }
    __syncthreads();   // W smem dead; region reused for h

    const int jl = mj * 16 + (lane >> 2);
    const int bl = (lane & 3) * 2;
    float* pp = sPrt + kw * (16 * 36);

    for (int t = 0; t < NT; t++) {
        const int td = d ? (NT - 1 - t) : t;

        // ---- stage h tile (16 rows, __ldcg batch, proven R12) ----
        if (t > 0) {
            const int p = t & 1;
            const __nv_bfloat16* srcHi = g_hhi[p] + (d * NB + b0) * NH;
            const __nv_bfloat16* srcLo = g_hlo[p] + (d * NB + b0) * NH;
            const int r  = tid >> 4;
            const int cc = tid & 15;
#pragma unroll
            for (int it = 0; it < 4; it++) {
                const int c16 = cc + it * 16;
                uint4 vh = __ldcg((const uint4*)(srcHi + r * NH) + c16);
                uint4 vl = __ldcg((const uint4*)(srcLo + r * NH) + c16);
                *(uint4*)((char*)sHhi + r * (EHS * 2) + c16 * 16) = vh;
                *(uint4*)((char*)sHlo + r * (EHS * 2) + c16 * 16) = vl;
            }
        }
        __syncthreads();

        // ---- MMA over this warp's K quarter (A from registers) ----
        if (t > 0) {
            float acc[2][4];
#pragma unroll
            for (int n = 0; n < 2; n++)
#pragma unroll
                for (int q = 0; q < 4; q++) acc[n][q] = 0.f;

#pragma unroll
            for (int q = 0; q < 8; q++) {
                uint32_t r0, r1, r2, r3, f0, f1, f2, f3;
                LDSM_X4(r0, r1, r2, r3, bHiBase + q * 32);
                LDSM_X4(f0, f1, f2, f3, bLoBase + q * 32);
                MMA_BF16(acc[0][0], acc[0][1], acc[0][2], acc[0][3],
                         aHi[q][0], aHi[q][1], aHi[q][2], aHi[q][3], r0, r1);
                MMA_BF16(acc[0][0], acc[0][1], acc[0][2], acc[0][3],
                         aHi[q][0], aHi[q][1], aHi[q][2], aHi[q][3], f0, f1);
                MMA_BF16(acc[0][0], acc[0][1], acc[0][2], acc[0][3],
                         aLo[q][0], aLo[q][1], aLo[q][2], aLo[q][3], r0, r1);
                MMA_BF16(acc[1][0], acc[1][1], acc[1][2], acc[1][3],
                         aHi[q][0], aHi[q][1], aHi[q][2], aHi[q][3], r2, r3);
                MMA_BF16(acc[1][0], acc[1][1], acc[1][2], acc[1][3],
                         aHi[q][0], aHi[q][1], aHi[q][2], aHi[q][3], f2, f3);
                MMA_BF16(acc[1][0], acc[1][1], acc[1][2], acc[1][3],
                         aLo[q][0], aLo[q][1], aLo[q][2], aLo[q][3], r2, r3);
            }
#pragma unroll
            for (int n = 0; n < 2; n++) {
                pp[(n * 8 + bl + 0) * 36 + jl]     = acc[n][0];
                pp[(n * 8 + bl + 1) * 36 + jl]     = acc[n][1];
                pp[(n * 8 + bl + 0) * 36 + jl + 8] = acc[n][2];
                pp[(n * 8 + bl + 1) * 36 + jl + 8] = acc[n][3];
            }
        }
        __syncthreads();

        // ---- owner epilogue: reduce + tanh + split + store + next init ----
        {
            float v0 = sStg[sr * 36 + sj + 0];
            float v1 = sStg[sr * 36 + sj + 1];
            if (t > 0) {
#pragma unroll
                for (int q = 0; q < 4; q++) {
                    v0 += sPrt[q * 576 + sr * 36 + sj + 0];
                    v1 += sPrt[q * 576 + sr * 36 + sj + 1];
                }
            }
            v0 = tanhf(v0); v1 = tanhf(v1);

            __nv_bfloat16 h0, h1, l0b, l1b;
            split_bf16(v0, h0, l0b);
            split_bf16(v1, h1, l1b);
            const int p1 = (t + 1) & 1;
            const int gidx = (d * NB + b0 + sr) * NH + j0 + sj;
            uint32_t phi = (uint32_t)__bfloat16_as_ushort(h0) |
                           ((uint32_t)__bfloat16_as_ushort(h1) << 16);
            uint32_t plo = (uint32_t)__bfloat16_as_ushort(l0b) |
                           ((uint32_t)__bfloat16_as_ushort(l1b) << 16);
            *(uint32_t*)(g_hhi[p1] + gidx) = phi;
            *(uint32_t*)(g_hlo[p1] + gidx) = plo;
            if (layer == 0) {
                const int li = (td * NB + b0 + sr) * (2 * NH) + d * NH + j0 + sj;
                *(uint32_t*)(g_l0hi + li) = phi;
                *(uint32_t*)(g_l0lo + li) = plo;
            }
            if (t == NT - 1) {
                const int slot = (layer ? 2 : 0) + d;
                const int di = (slot * NB + b0 + sr) * NH + j0 + sj;
                *(uint32_t*)(g_dhhi[0] + di) = phi;
                *(uint32_t*)(g_dhlo[0] + di) = plo;
            }

            if (t < NT - 1) {
                const int td2 = d ? (NT - 2 - t) : (t + 1);
                float n0, n1;
                if (layer == 0) {
                    const float* xr = x + ((b0 + sr) * NT + td2) * NIN;
                    const float x0 = xr[0], x1 = xr[1], x2 = xr[2];
                    n0 = bias0 + x0 * wi[0] + x1 * wi[1] + x2 * wi[2];
                    n1 = bias1 + x0 * wi[3] + x1 * wi[4] + x2 * wi[5];
                } else {
                    float2 v = __ldg((const float2*)&g_xs1[((d * NT + td2) * NB + b0 + sr) * NH + j0 + sj]);
                    n0 = v.x; n1 = v.y;
                }
                sStg[sr * 36 + sj + 0] = n0;
                sStg[sr * 36 + sj + 1] = n1;
            }
        }

        if (t < NT - 1)
            group_barrier(grp, 16);
    }
}

// ---------------------------------------------------------------------------
// xs1 via tensor cores (R12, unchanged): 2-stage cp.async pipelined GEMM.
// ---------------------------------------------------------------------------
__device__ __forceinline__ void xs1_stage(uint32_t sbase, int d, int j0, int m0,
                                          int k0, int tid)
{
    const int r  = tid >> 3;
    const int c8 = (tid & 7) * 8;
#pragma unroll
    for (int rr = r; rr < 128; rr += 32) {
        const int gi = (m0 + rr) * (2 * NH) + k0 + c8;
        CP_ASYNC16(sbase + (uint32_t)((rr * XAS + c8) * 2),        g_l0hi + gi);
        CP_ASYNC16(sbase + (uint32_t)(X_SA + (rr * XAS + c8) * 2), g_l0lo + gi);
    }
#pragma unroll
    for (int rr = r; rr < 64; rr += 32) {
        const int gi = (d * NH + j0 + rr) * (2 * NH) + k0 + c8;
        CP_ASYNC16(sbase + (uint32_t)(2 * X_SA + (rr * XAS + c8) * 2),        g_xWhi + gi);
        CP_ASYNC16(sbase + (uint32_t)(2 * X_SA + X_SB + (rr * XAS + c8) * 2), g_xWlo + gi);
    }
    CP_COMMIT();
}

__global__ void __launch_bounds__(256) xs1_mma(
    const float* __restrict__ bih, const float* __restrict__ bhh)
{
    extern __shared__ char sm[];
    const uint32_t smBase = s2u(sm);

    const int d  = blockIdx.z;
    const int j0 = blockIdx.x * 64;
    const int m0 = blockIdx.y * 128;
    const int tid  = threadIdx.x;
    const int lane = tid & 31;
    const int warp = tid >> 5;
    const int wm = warp & 3;
    const int wn = warp >> 2;

    const int ag = lane >> 3, ar = lane & 7;
    const uint32_t aOff = (uint32_t)((wm * 32 + (ag & 1) * 8 + ar) * XAS + (ag >> 1) * 8) * 2;
    const uint32_t bOff = (uint32_t)(2 * X_SA) +
        (uint32_t)((wn * 32 + (lane >> 4) * 8 + (lane & 7)) * XAS + ((lane >> 3) & 1) * 8) * 2;

    float acc[2][4][4];
#pragma unroll
    for (int i = 0; i < 2; i++)
#pragma unroll
        for (int n = 0; n < 4; n++)
#pragma unroll
            for (int q = 0; q < 4; q++) acc[i][n][q] = 0.f;

    xs1_stage(smBase, d, j0, m0, 0, tid);

    for (int c = 0; c < 16; c++) {
        if (c < 15)
            xs1_stage(smBase + ((c + 1) & 1) * X_STAGE, d, j0, m0, (c + 1) * 64, tid);
        if (c < 15) { CP_WAIT1(); } else { CP_WAIT0(); }
        __syncthreads();

        const uint32_t aBase = smBase + (c & 1) * X_STAGE + aOff;
        const uint32_t bBase = smBase + (c & 1) * X_STAGE + bOff;

#pragma unroll
        for (int kk = 0; kk < 4; kk++) {
            uint32_t ah[2][4], al[2][4];
#pragma unroll
            for (int mt = 0; mt < 2; mt++) {
                const uint32_t addr = aBase + (uint32_t)(mt * 16 * XAS + kk * 16) * 2;
                LDSM_X4(ah[mt][0], ah[mt][1], ah[mt][2], ah[mt][3], addr);
                LDSM_X4(al[mt][0], al[mt][1], al[mt][2], al[mt][3], addr + X_SA);
            }
#pragma unroll
            for (int np = 0; np < 2; np++) {
                const uint32_t addr = bBase + (uint32_t)(np * 16 * XAS + kk * 16) * 2;
                uint32_t bh0, bh1, bh2, bh3, bl0, bl1, bl2, bl3;
                LDSM_X4(bh0, bh1, bh2, bh3, addr);
                LDSM_X4(bl0, bl1, bl2, bl3, addr + X_SB);
#pragma unroll
                for (int mt = 0; mt < 2; mt++) {
                    float* a0 = acc[mt][np * 2 + 0];
                    float* a1 = acc[mt][np * 2 + 1];
                    MMA_BF16(a0[0], a0[1], a0[2], a0[3],
                             ah[mt][0], ah[mt][1], ah[mt][2], ah[mt][3], bh0, bh1);
                    MMA_BF16(a0[0], a0[1], a0[2], a0[3],
                             ah[mt][0], ah[mt][1], ah[mt][2], ah[mt][3], bl0, bl1);
                    MMA_BF16(a0[0], a0[1], a0[2], a0[3],
                             al[mt][0], al[mt][1], al[mt][2], al[mt][3], bh0, bh1);
                    MMA_BF16(a1[0], a1[1], a1[2], a1[3],
                             ah[mt][0], ah[mt][1], ah[mt][2], ah[mt][3], bh2, bh3);
                    MMA_BF16(a1[0], a1[1], a1[2], a1[3],
                             ah[mt][0], ah[mt][1], ah[mt][2], ah[mt][3], bl2, bl3);
                    MMA_BF16(a1[0], a1[1], a1[2], a1[3],
                             al[mt][0], al[mt][1], al[mt][2], al[mt][3], bh2, bh3);
                }
            }
        }
        __syncthreads();
    }

#pragma unroll
    for (int nt = 0; nt < 4; nt++) {
        const int j = j0 + wn * 32 + nt * 8 + (lane & 3) * 2;
        const float bj0 = __ldg(&bih[(2 + d) * NH + j])     + __ldg(&bhh[(2 + d) * NH + j]);
        const float bj1 = __ldg(&bih[(2 + d) * NH + j + 1]) + __ldg(&bhh[(2 + d) * NH + j + 1]);
#pragma unroll
        for (int mt = 0; mt < 2; mt++) {
            const int m = m0 + wm * 32 + mt * 16 + (lane >> 2);
            *(float2*)&g_xs1[(d * NT * NB + m) * NH + j] =
                make_float2(acc[mt][nt][0] + bj0, acc[mt][nt][1] + bj1);
            *(float2*)&g_xs1[(d * NT * NB + m + 8) * NH + j] =
                make_float2(acc[mt][nt][2] + bj0, acc[mt][nt][3] + bj1);
        }
    }
}

// ---------------------------------------------------------------------------
// Decoder W prefetch: Wihr[lB-1] -> cols 0-511 (if lB>=1), Whh[lR] -> cols 512+
// ---------------------------------------------------------------------------
__device__ __forceinline__ void dec_prefetch_W(int lB, int lR, int j0, int tid,
                                               uint32_t swhi, uint32_t swlo)
{
    const int r  = tid >> 3;
    const int c8 = tid & 7;
    if (lB >= 1) {
        const __nv_bfloat16* shi = g_dWhi + WIHR_OFF + (lB - 1) * WMAT + (j0 + r) * NH;
        const __nv_bfloat16* slo = g_dWlo + WIHR_OFF + (lB - 1) * WMAT + (j0 + r) * NH;
#pragma unroll
        for (int c = c8; c < 64; c += 8) {
            CP_ASYNC16(swhi + (uint32_t)(r * DEHS + c * 8) * 2, shi + c * 8);
            CP_ASYNC16(swlo + (uint32_t)(r * DEHS + c * 8) * 2, slo + c * 8);
        }
    }
    {
        const __nv_bfloat16* rhi = g_dWhi + lR * WMAT + (j0 + r) * NH;
        const __nv_bfloat16* rlo = g_dWlo + lR * WMAT + (j0 + r) * NH;
#pragma unroll
        for (int c = c8; c < 64; c += 8) {
            CP_ASYNC16(swhi + (uint32_t)(r * DEHS + 512 + c * 8) * 2, rhi + c * 8);
            CP_ASYNC16(swlo + (uint32_t)(r * DEHS + 512 + c * 8) * 2, rlo + c * 8);
        }
    }
    CP_COMMIT();
}

// ---------------------------------------------------------------------------
// Persistent decoder (R14): warp-specialized. Warps 0-3 (role 0) run the
// critical input-GEMM chain; warps 4-7 (role 1) compute next-step recurrent
// GEMMs (Whh_l . h_l) off the critical path, sharing the same staged h tile.
// Schedule: phase P_l(t) -> role1 computes R_{(l+3)%4} for its consumer phase;
// prologue seeds R_0..R_2(0) from hn.
// ---------------------------------------------------------------------------
__global__ void __launch_bounds__(256) dec_persist(
    const float* __restrict__ x,    const float* __restrict__ Wih0,
    const float* __restrict__ Wihr, const float* __restrict__ Whh,
    const float* __restrict__ bih,  const float* __restrict__ bhh,
    const float* __restrict__ linW, const float* __restrict__ linb,
    float* __restrict__ out)
{
    extern __shared__ char sm[];
    __nv_bfloat16* sWhi = (__nv_bfloat16*)(sm + OFF_DWHI);
    __nv_bfloat16* sWlo = (__nv_bfloat16*)(sm + OFF_DWLO);
    __nv_bfloat16* sHhi = (__nv_bfloat16*)(sm + OFF_DHHI);
    __nv_bfloat16* sHlo = (__nv_bfloat16*)(sm + OFF_DHLO);
    float*         sStg = (float*)(sm + OFF_DSTG);   // [16][36]
    float*         sPrt = (float*)(sm + OFF_DPRT);   // [2][16][36] (B partials)
    float*         sRec = (float*)(sm + OFF_DREC);   // [4][2][16][36]

    __shared__ float s_dec[16][3];

    const int jt = blockIdx.x & 15;
    const int bt = blockIdx.x >> 4;
    const int grp = 8 + bt;
    const int j0 = jt * 32;
    const int b0 = bt * 16;
    const int tid  = threadIdx.x;
    const int lane = tid & 31;
    const int warp = tid >> 5;
    const int mj   = warp & 1;          // j half (16 rows)
    const int kh   = (warp >> 1) & 1;   // k half (256 cols)
    const int role = warp >> 2;         // 0 = input chain, 1 = recurrent

    // one-time: convert decoder weights to bf16 hi/lo (grid-strided)
    {
        const int stride4 = DEC_CTAS * 256 * 4;
        const int g4 = (blockIdx.x * 256 + tid) * 4;
        for (int i = g4; i < 4 * WMAT; i += stride4) {
            float4 w = *(const float4*)&Whh[i];
            split_bf16(w.x, g_dWhi[i + 0], g_dWlo[i + 0]);
            split_bf16(w.y, g_dWhi[i + 1], g_dWlo[i + 1]);
            split_bf16(w.z, g_dWhi[i + 2], g_dWlo[i + 2]);
            split_bf16(w.w, g_dWhi[i + 3], g_dWlo[i + 3]);
        }
        for (int i = g4; i < 3 * WMAT; i += stride4) {
            float4 w = *(const float4*)&Wihr[i];
            split_bf16(w.x, g_dWhi[WIHR_OFF + i + 0], g_dWlo[WIHR_OFF + i + 0]);
            split_bf16(w.y, g_dWhi[WIHR_OFF + i + 1], g_dWlo[WIHR_OFF + i + 1]);
            split_bf16(w.z, g_dWhi[WIHR_OFF + i + 2], g_dWlo[WIHR_OFF + i + 2]);
            split_bf16(w.w, g_dWhi[WIHR_OFF + i + 3], g_dWlo[WIHR_OFF + i + 3]);
        }
    }
    if (tid < 16) {
        const float* xr = x + ((b0 + tid) * NT + (NT - 1)) * NIN;
        s_dec[tid][0] = xr[0];
        s_dec[tid][1] = xr[1];
        s_dec[tid][2] = xr[2];
    }
    grid_barrier(DEC_CTAS);

    // ---- ldmatrix bases ----
    const int ag = lane >> 3, ar = lane & 7;
    const uint32_t aOff = (uint32_t)((mj * 16 + (ag & 1) * 8 + ar) * DEHS
                                     + (ag >> 1) * 8 + role * 512 + kh * 256) * 2;
    const uint32_t aHiBase = s2u(sWhi) + aOff;
    const uint32_t aLoBase = s2u(sWlo) + aOff;
    const uint32_t bOff = (uint32_t)(((lane >> 4) * 8 + (lane & 7)) * DHS
                                     + ((lane >> 3) & 1) * 8 + kh * 256) * 2;
    const uint32_t bHiBase = s2u(sHhi) + bOff;
    const uint32_t bLoBase = s2u(sHlo) + bOff;

    const int sr = tid >> 4;
    const int sj = (tid & 15) * 2;
    const int jl = mj * 16 + (lane >> 2);
    const int bl = (lane & 3) * 2;

    const float linw0 = __ldg(&linW[j0 + sj + 0]);
    const float linw1 = __ldg(&linW[j0 + sj + 1]);
    const float lb0   = __ldg(&linb[0]);

    // ---- stage-h helper captured by lambda-ish macro (inline each use) ----
    // ---- prologue: seed sRec[0..2] = Whh_l . hn_l (local, no barriers) ----
    for (int l = 0; l < 3; l++) {
        {   // stage hn_l + Whh_l (R region)
            const int r   = tid >> 4;
            const int c16 = tid & 15;
            const __nv_bfloat16* rhi = g_dhhi[0] + (l * NB + b0 + r) * NH;
            const __nv_bfloat16* rlo = g_dhlo[0] + (l * NB + b0 + r) * NH;
#pragma unroll
            for (int c = c16; c < 64; c += 16) {
                CP_ASYNC16(s2u(sHhi) + (uint32_t)(r * DHS + c * 8) * 2, rhi + c * 8);
                CP_ASYNC16(s2u(sHlo) + (uint32_t)(r * DHS + c * 8) * 2, rlo + c * 8);
            }
            const int wr = tid >> 3, wc = tid & 7;
            const __nv_bfloat16* whi = g_dWhi + l * WMAT + (j0 + wr) * NH;
            const __nv_bfloat16* wlo = g_dWlo + l * WMAT + (j0 + wr) * NH;
#pragma unroll
            for (int c = wc; c < 64; c += 8) {
                CP_ASYNC16(s2u(sWhi) + (uint32_t)(wr * DEHS + 512 + c * 8) * 2, whi + c * 8);
                CP_ASYNC16(s2u(sWlo) + (uint32_t)(wr * DEHS + 512 + c * 8) * 2, wlo + c * 8);
            }
            CP_COMMIT();
        }
        CP_WAIT0();
        __syncthreads();
        if (role == 1) {
            float c00 = 0.f, c01 = 0.f, c02 = 0.f, c03 = 0.f;
            float c10 = 0.f, c11 = 0.f, c12 = 0.f, c13 = 0.f;
            uint32_t aHi = aHiBase, aLo = aLoBase, bHi = bHiBase, bLo = bLoBase;
#pragma unroll 4
            for (int kk = 0; kk < 16; kk++) {
                uint32_t a0, a1, a2, a3, e0, e1, e2, e3;
                uint32_t r0, r1, r2, r3, f0, f1, f2, f3;
                LDSM_X4(a0, a1, a2, a3, aHi);
                LDSM_X4(e0, e1, e2, e3, aLo);
                LDSM_X4(r0, r1, r2, r3, bHi);
                LDSM_X4(f0, f1, f2, f3, bLo);
                MMA_BF16(c00, c01, c02, c03, a0, a1, a2, a3, r0, r1);
                MMA_BF16(c00, c01, c02, c03, a0, a1, a2, a3, f0, f1);
                MMA_BF16(c00, c01, c02, c03, e0, e1, e2, e3, r0, r1);
                MMA_BF16(c10, c11, c12, c13, a0, a1, a2, a3, r2, r3);
                MMA_BF16(c10, c11, c12, c13, a0, a1, a2, a3, f2, f3);
                MMA_BF16(c10, c11, c12, c13, e0, e1, e2, e3, r2, r3);
                aHi += 32; aLo += 32; bHi += 32; bLo += 32;
            }
            float* pp = sRec + (l * 2 + kh) * 576;
            pp[(bl + 0) * 36 + jl]     = c00;
            pp[(bl + 1) * 36 + jl]     = c01;
            pp[(bl + 0) * 36 + jl + 8] = c02;
            pp[(bl + 1) * 36 + jl + 8] = c03;
            pp[(bl + 8) * 36 + jl]     = c10;
            pp[(bl + 9) * 36 + jl]     = c11;
            pp[(bl + 8) * 36 + jl + 8] = c12;
            pp[(bl + 9) * 36 + jl + 8] = c13;
        }
        __syncthreads();
    }
    // prefetch for P0(0): Whh_3 only
    dec_prefetch_W(0, 3, j0, tid, s2u(sWhi), s2u(sWlo));

    for (int t = 0; t < NTGT; t++) {
        const int p = t & 1;

        // ---- feedback from step t-1: sum 16 per-jt partials ----
        if (t > 0) {
            if (tid < 16) {
                float o0 = lb0;
#pragma unroll
                for (int q = 0; q < 16; q++)
                    o0 += __ldcg(&g_o0p[p][q * NB + b0 + tid]);
                if (jt == 0) out[(b0 + tid) * NTGT + (t - 1)] = o0;
                float s1 = s_dec[tid][0] - o0;
                float s2 = s_dec[tid][1] - s1;
                s_dec[tid][0] = o0;
                s_dec[tid][1] = s1;
                s_dec[tid][2] = s2;
            }
            __syncthreads();
        }

        for (int l = 0; l < 4; l++) {
            // ---- stage h tile: l==0 -> h_3(t-1) [g_dh(p)]; else h_{l-1}(t) ----
            {
                const int r   = tid >> 4;
                const int c16 = tid & 15;
                const __nv_bfloat16* rhi;
                const __nv_bfloat16* rlo;
                if (l == 0) {
                    rhi = g_dhhi[p] + (3 * NB + b0 + r) * NH;
                    rlo = g_dhlo[p] + (3 * NB + b0 + r) * NH;
                } else {
                    rhi = g_dhhi[1 - p] + ((l - 1) * NB + b0 + r) * NH;
                    rlo = g_dhlo[1 - p] + ((l - 1) * NB + b0 + r) * NH;
                }
#pragma unroll
                for (int c = c16; c < 64; c += 16) {
                    CP_ASYNC16(s2u(sHhi) + (uint32_t)(r * DHS + c * 8) * 2, rhi + c * 8);
                    CP_ASYNC16(s2u(sHlo) + (uint32_t)(r * DHS + c * 8) * 2, rlo + c * 8);
                }
                CP_COMMIT();
            }
            // ---- stage init ----
            {
                float v0 = bih[l * NH + j0 + sj + 0] + bhh[l * NH + j0 + sj + 0];
                float v1 = bih[l * NH + j0 + sj + 1] + bhh[l * NH + j0 + sj + 1];
                if (l == 0) {
                    const float i0 = s_dec[sr][0], i1 = s_dec[sr][1], i2 = s_dec[sr][2];
                    const float* wp = Wih0 + (j0 + sj) * NIN;
                    v0 += i0 * wp[0] + i1 * wp[1] + i2 * wp[2];
                    v1 += i0 * wp[3] + i1 * wp[4] + i2 * wp[5];
                }
                sStg[sr * 36 + sj + 0] = v0;
                sStg[sr * 36 + sj + 1] = v1;
            }
            CP_WAIT0();     // h (this phase) + W (prefetched last phase)
            __syncthreads();

            // ---- MMA: role0 = input gemm (l>=1); role1 = recurrent prefill ----
            if (role == 1 || l >= 1) {
                float c00 = 0.f, c01 = 0.f, c02 = 0.f, c03 = 0.f;
                float c10 = 0.f, c11 = 0.f, c12 = 0.f, c13 = 0.f;
                uint32_t aHi = aHiBase, aLo = aLoBase, bHi = bHiBase, bLo = bLoBase;
#pragma unroll 4
                for (int kk = 0; kk < 16; kk++) {
                    uint32_t a0, a1, a2, a3, e0, e1, e2, e3;
                    uint32_t r0, r1, r2, r3, f0, f1, f2, f3;
                    LDSM_X4(a0, a1, a2, a3, aHi);
                    LDSM_X4(e0, e1, e2, e3, aLo);
                    LDSM_X4(r0, r1, r2, r3, bHi);
                    LDSM_X4(f0, f1, f2, f3, bLo);
                    MMA_BF16(c00, c01, c02, c03, a0, a1, a2, a3, r0, r1);
                    MMA_BF16(c00, c01, c02, c03, a0, a1, a2, a3, f0, f1);
                    MMA_BF16(c00, c01, c02, c03, e0, e1, e2, e3, r0, r1);
                    MMA_BF16(c10, c11, c12, c13, a0, a1, a2, a3, r2, r3);
                    MMA_BF16(c10, c11, c12, c13, a0, a1, a2, a3, f2, f3);
                    MMA_BF16(c10, c11, c12, c13, e0, e1, e2, e3, r2, r3);
                    aHi += 32; aLo += 32; bHi += 32; bLo += 32;
                }
                float* pp = (role == 0) ? (sPrt + kh * 576)
                                        : (sRec + (((l + 3) & 3) * 2 + kh) * 576);
                pp[(bl + 0) * 36 + jl]     = c00;
                pp[(bl + 1) * 36 + jl]     = c01;
                pp[(bl + 0) * 36 + jl + 8] = c02;
                pp[(bl + 1) * 36 + jl + 8] = c03;
                pp[(bl + 8) * 36 + jl]     = c10;
                pp[(bl + 9) * 36 + jl]     = c11;
                pp[(bl + 8) * 36 + jl + 8] = c12;
                pp[(bl + 9) * 36 + jl + 8] = c13;
            }
            __syncthreads();

            // ---- prefetch next phase's W (overlaps epilogue + barrier) ----
            if (!(t == NTGT - 1 && l == 3)) {
                const int ln = (l + 1) & 3;
                dec_prefetch_W(ln, (ln + 3) & 3, j0, tid, s2u(sWhi), s2u(sWlo));
            }

            // ---- owner epilogue: init + B partials + sRec[l], tanh, store ----
            {
                float v0 = sStg[sr * 36 + sj + 0];
                float v1 = sStg[sr * 36 + sj + 1];
                if (l >= 1) {
#pragma unroll
                    for (int q = 0; q < 2; q++) {
                        v0 += sPrt[q * 576 + sr * 36 + sj + 0];
                        v1 += sPrt[q * 576 + sr * 36 + sj + 1];
                    }
                }
#pragma unroll
                for (int q = 0; q < 2; q++) {
                    v0 += sRec[(l * 2 + q) * 576 + sr * 36 + sj + 0];
                    v1 += sRec[(l * 2 + q) * 576 + sr * 36 + sj + 1];
                }
                v0 = tanhf(v0); v1 = tanhf(v1);
                __nv_bfloat16 h0, h1, l0b, l1b;
                split_bf16(v0, h0, l0b);
                split_bf16(v1, h1, l1b);
                const int idx = (l * NB + b0 + sr) * NH + j0 + sj;
                uint32_t phi = (uint32_t)__bfloat16_as_ushort(h0) |
                               ((uint32_t)__bfloat16_as_ushort(h1) << 16);
                uint32_t plo = (uint32_t)__bfloat16_as_ushort(l0b) |
                               ((uint32_t)__bfloat16_as_ushort(l1b) << 16);
                *(uint32_t*)(g_dhhi[1 - p] + idx) = phi;
                *(uint32_t*)(g_dhlo[1 - p] + idx) = plo;

                if (l == 3) {
                    float part = v0 * linw0 + v1 * linw1;
#pragma unroll
                    for (int o = 8; o; o >>= 1)
                        part += __shfl_down_sync(0xffffffffu, part, o, 16);
                    if ((lane & 15) == 0)
                        g_o0p[1 - p][jt * NB + b0 + sr] = part;
                }
            }

            group_barrier(grp, 16);
        }
    }

    // ---- final output (t = NTGT-1) ----
    if (tid < 16 && jt == 0) {
        float o0 = lb0;
#pragma unroll
        for (int q = 0; q < 16; q++)
            o0 += __ldcg(&g_o0p[NTGT & 1][q * NB + b0 + tid]);
        out[(b0 + tid) * NTGT + (NTGT - 1)] = o0;
    }
}

// ---------------------------------------------------------------------------
// Launch sequence (graph-capturable: kernel launches only)
// ---------------------------------------------------------------------------
extern "C" void kernel_launch(void* const* d_in, const int* in_sizes, int n_in,
                              void* d_out, int out_size)
{
    const float* x        = (const float*)d_in[0];
    const float* enc_Wih0 = (const float*)d_in[2];
    const float* enc_Whh0 = (const float*)d_in[3];
    const float* enc_Wih1 = (const float*)d_in[4];
    const float* enc_Whh1 = (const float*)d_in[5];
    const float* enc_bih  = (const float*)d_in[6];
    const float* enc_bhh  = (const float*)d_in[7];
    const float* dec_Wih0 = (const float*)d_in[8];
    const float* dec_Wihr = (const float*)d_in[9];
    const float* dec_Whh  = (const float*)d_in[10];
    const float* dec_bih  = (const float*)d_in[11];
    const float* dec_bhh  = (const float*)d_in[12];
    const float* lin_W    = (const float*)d_in[13];
    const float* lin_b    = (const float*)d_in[14];
    float* out = (float*)d_out;

    cudaFuncSetAttribute(enc_mma, cudaFuncAttributeMaxDynamicSharedMemorySize,
                         ENC_SMEM);
    cudaFuncSetAttribute(dec_persist, cudaFuncAttributeMaxDynamicSharedMemorySize,
                         DEC_SMEM);
    cudaFuncSetAttribute(xs1_mma, cudaFuncAttributeMaxDynamicSharedMemorySize,
                         XS1_SMEM);

    // Pre-split Wih1 (independent of encoder)
    split_wih1<<<1024, 256>>>(enc_Wih1);

    // Encoder layer 0
    enc_mma<<<ENC_CTAS, 256, ENC_SMEM>>>(x, enc_Wih0, enc_Whh0,
                                         enc_bih, enc_bhh, 0);

    // Layer-1 input terms, pipelined tensor-core GEMM
    xs1_mma<<<dim3(8, 128, 2), 256, XS1_SMEM>>>(enc_bih, enc_bhh);

    // Encoder layer 1
    enc_mma<<<ENC_CTAS, 256, ENC_SMEM>>>(x, enc_Wih0, enc_Whh1,
                                         enc_bih, enc_bhh, 1);

    // Decoder (warp-specialized recurrent prefill)
    dec_persist<<<DEC_CTAS, 256, DEC_SMEM>>>(x, dec_Wih0, dec_Wihr, dec_Whh,
                                             dec_bih, dec_bhh, lin_W, lin_b, out);
}